// round 2
// baseline (speedup 1.0000x reference)
#include <cuda_runtime.h>
#include <cstdint>

#define K3          27
#define PAIRS_PER_K 131072
#define N_VOX       262144
#define C_IN        32
#define C_OUT       32
#define M_TOTAL     (K3 * PAIRS_PER_K)
#define TPB         256

// Pairs handled per block: 8 warps x 2 pairs/iter x NITER iters.
#define NITER       128
#define PPB         (8 * 2 * NITER)          // 2048, divides PAIRS_PER_K
#define BLOCKS_PER_K (PAIRS_PER_K / PPB)     // 64

// ---------------------------------------------------------------------------
// Kernel 1: initialize output with bias (d_out is poisoned by harness).
// ---------------------------------------------------------------------------
__global__ void init_bias_kernel(float4* __restrict__ out,
                                 const float4* __restrict__ bias4) {
    int t = blockIdx.x * blockDim.x + threadIdx.x;
    if (t < N_VOX * 8) {
        out[t] = bias4[t & 7];
    }
}

// ---------------------------------------------------------------------------
// Kernel 2: warp-collective gather -> 32x32 GEMV -> coalesced atomic scatter.
//
// 16 lanes per pair, 2 output channels per lane (packed f32x2 FMA).
// Half-warp h = lane>>4 owns pair (base + 2*it + h).
//   - W[k] columns (2m, 2m+1) are register-resident (32 x u64 per lane).
//   - x row gathered coalesced: lane m loads float2 -> 1 line per pair.
//   - x[i] broadcast to the half-warp via __shfl_sync (no L1 traffic).
//   - scatter: red.global.add.v2.f32, 16 lanes cover the 128B output row.
// ---------------------------------------------------------------------------
__global__ void __launch_bounds__(TPB, 2)
scatter_conv_kernel(const float* __restrict__ in_feature,   // [N_VOX][32]
                    const float* __restrict__ kernel_w,     // [K3][32][32]
                    const int2*  __restrict__ nbmap,        // [M] (src,dst)
                    float*       __restrict__ out)          // [N_VOX][32]
{
    const int lane  = threadIdx.x & 31;
    const int warp  = threadIdx.x >> 5;
    const int m     = lane & 15;      // channel-pair index: channels 2m, 2m+1
    const int hbase = lane & 16;      // shuffle source base for this half-warp

    const int k = blockIdx.x / BLOCKS_PER_K;

    // Register-resident W: lane holds W[k][i][2m..2m+1] for all 32 input ch.
    unsigned long long Wreg[32];
    const float* wk = kernel_w + (size_t)k * (C_IN * C_OUT) + 2 * m;
#pragma unroll
    for (int i = 0; i < 32; i++) {
        Wreg[i] = *reinterpret_cast<const unsigned long long*>(wk + i * C_OUT);
    }

    int pair = blockIdx.x * PPB + warp * (2 * NITER) + (lane >> 4);

#pragma unroll 1
    for (int it = 0; it < NITER; it++, pair += 2) {
        const int2 ij = nbmap[pair];

        // Coalesced gather: half-warp covers the 128B input row.
        const unsigned long long xx = *reinterpret_cast<const unsigned long long*>(
            in_feature + (size_t)ij.x * C_IN + 2 * m);
        const unsigned int xlo = (unsigned int)xx;
        const unsigned int xhi = (unsigned int)(xx >> 32);

        unsigned long long acc = 0ull;
#pragma unroll
        for (int i = 0; i < 32; i++) {
            // Broadcast x[i] from the lane of this half-warp that holds it.
            unsigned int w = __shfl_sync(0xffffffffu,
                                         (i & 1) ? xhi : xlo,
                                         hbase + (i >> 1));
            unsigned long long x2;
            asm("mov.b64 %0, {%1, %1};" : "=l"(x2) : "r"(w));
            asm("fma.rn.f32x2 %0, %1, %2, %0;"
                : "+l"(acc) : "l"(x2), "l"(Wreg[i]));
        }

        // Coalesced vector scatter-add: 16 lanes cover the 128B output row.
        unsigned int a0, a1;
        asm("mov.b64 {%0,%1}, %2;" : "=r"(a0), "=r"(a1) : "l"(acc));
        asm volatile("red.global.add.v2.f32 [%0], {%1,%2};"
                     :: "l"(out + (size_t)ij.y * C_OUT + 2 * m),
                        "f"(__uint_as_float(a0)), "f"(__uint_as_float(a1))
                     : "memory");
    }
}

// ---------------------------------------------------------------------------
// Inputs (metadata order): in_feature f32[N_VOX,32], kernel f32[27,32,32],
// bias f32[32], nbmap i32[M,2], nbsizes i32[27]. Output f32[N_VOX,32].
// ---------------------------------------------------------------------------
extern "C" void kernel_launch(void* const* d_in, const int* in_sizes, int n_in,
                              void* d_out, int out_size) {
    const float*  in_feature = (const float*)d_in[0];
    const float*  kernel_w   = (const float*)d_in[1];
    const float4* bias4      = (const float4*)d_in[2];
    const int2*   nbmap      = (const int2*)d_in[3];
    float*        out        = (float*)d_out;

    init_bias_kernel<<<(N_VOX * 8 + 255) / 256, 256>>>((float4*)out, bias4);
    scatter_conv_kernel<<<M_TOTAL / PPB, TPB>>>(in_feature, kernel_w, nbmap, out);
}

// round 4
// speedup vs baseline: 2.1645x; 2.1645x over previous
#include <cuda_runtime.h>
#include <cstdint>

#define K3          27
#define PAIRS_PER_K 131072
#define N_VOX       262144
#define C_IN        32
#define C_OUT       32
#define M_TOTAL     (K3 * PAIRS_PER_K)

#define TILE        128                     // pairs per MMA tile (8 warps x 16)
#define NT          8                       // tiles per block (same k)
#define TPB         256
#define TILES_PER_K (PAIRS_PER_K / TILE)    // 1024 (divisible by NT)
#define GRID        (M_TOTAL / TILE / NT)   // 3456
#define RS          36                      // A smem row stride in floats (144B):
                                            // 16B-aligned for cp.async, bank-conflict-free frags

// ---------------------------------------------------------------------------
// Kernel 1: initialize output with bias (d_out is poisoned by harness).
// ---------------------------------------------------------------------------
__global__ void init_bias_kernel(float4* __restrict__ out,
                                 const float4* __restrict__ bias4) {
    int t = blockIdx.x * blockDim.x + threadIdx.x;
    if (t < N_VOX * 8) out[t] = bias4[t & 7];
}

__device__ __forceinline__ uint32_t f2tf32(float x) {
    uint32_t r;
    asm("cvt.rna.tf32.f32 %0, %1;" : "=r"(r) : "f"(x));
    return r;
}

// ---------------------------------------------------------------------------
// Kernel 2: cp.async gather -> tf32 mma.sync (m16n8k8) -> shfl-merged
//           coalesced red.global.add.v4 scatter.
// Per block: NT tiles of 128 pairs, all same kernel offset k.
// Per warp per tile: 16 pairs (m16 x n32 x k32 = 16 HMMA).
// ---------------------------------------------------------------------------
__global__ void __launch_bounds__(TPB, 2)
conv_mma_kernel(const float* __restrict__ in_feature,   // [N_VOX][32]
                const float* __restrict__ kernel_w,     // [K3][32][32]
                const int*   __restrict__ nbmap,        // [M][2] (src,dst)
                float*       __restrict__ out)          // [N_VOX][32]
{
    __shared__ __align__(16) float As[2][TILE * RS];    // 2 x 18432B

    const int tid  = threadIdx.x;
    const int wid  = tid >> 5;
    const int lane = tid & 31;

    const int tile0 = blockIdx.x * NT;
    const int k     = tile0 / TILES_PER_K;

    // ---- B fragments: W[k] register-resident as tf32 (loaded once) ----
    // B[j][s]: n8-tile j, k8-step s.  b0=(k=8s+lane%4, n=8j+lane/4), b1: k+4.
    uint32_t B[4][4][2];
    {
        const float* wk = kernel_w + (size_t)k * (C_IN * C_OUT);
        const int bk = lane & 3, bn = lane >> 2;
#pragma unroll
        for (int j = 0; j < 4; j++)
#pragma unroll
            for (int s = 0; s < 4; s++) {
                B[j][s][0] = f2tf32(wk[(8 * s + bk    ) * C_OUT + 8 * j + bn]);
                B[j][s][1] = f2tf32(wk[(8 * s + bk + 4) * C_OUT + 8 * j + bn]);
            }
    }

    // ---- gather tile t into buffer buf: 1024 x cp.async.cg 16B ----
    auto gather = [&](int t, int buf) {
        const size_t pbase = (size_t)(tile0 + t) * TILE;
        const int ch = tid & 7;
#pragma unroll
        for (int jj = 0; jj < 4; jj++) {
            const int row = (tid >> 3) + 32 * jj;
            const int v   = nbmap[2 * (pbase + row)];         // src voxel
            const float* src = in_feature + (size_t)v * C_IN + ch * 4;
            const uint32_t dst =
                (uint32_t)__cvta_generic_to_shared(&As[buf][row * RS + ch * 4]);
            asm volatile("cp.async.cg.shared.global [%0], [%1], 16;"
                         :: "r"(dst), "l"(src));
        }
        asm volatile("cp.async.commit_group;" ::: "memory");
    };

    gather(0, 0);

    const int ar   = lane >> 2;                       // frag row-in-8
    const int ac   = lane & 3;                        // frag col-in-4
    const int rloc = 16 * wid + ar + 8 * (lane & 1);  // this lane's output row
    const int colb = (lane & 2) << 1;                 // 0 or 4
    const bool odd = lane & 1;

    for (int t = 0; t < NT; t++) {
        const int buf = t & 1;
        asm volatile("cp.async.wait_group 0;" ::: "memory");
        __syncthreads();                              // A(t) ready; buf^1 free

        if (t + 1 < NT) gather(t + 1, buf ^ 1);       // overlap with compute

        // destination voxel for this lane's merged row
        const int y = nbmap[2 * ((size_t)(tile0 + t) * TILE + rloc) + 1];

        float D[4][4];
#pragma unroll
        for (int j = 0; j < 4; j++)
#pragma unroll
            for (int q = 0; q < 4; q++) D[j][q] = 0.f;

        const float* Ab = &As[buf][(16 * wid + ar) * RS];
#pragma unroll
        for (int s = 0; s < 4; s++) {
            // A frags: a0=(r, 8s+ac) a1=(r+8, ..) a2=(r, ..+4) a3=(r+8, ..+4)
            uint32_t a0 = f2tf32(Ab[8 * s + ac]);
            uint32_t a1 = f2tf32(Ab[8 * RS + 8 * s + ac]);
            uint32_t a2 = f2tf32(Ab[8 * s + ac + 4]);
            uint32_t a3 = f2tf32(Ab[8 * RS + 8 * s + ac + 4]);
#pragma unroll
            for (int j = 0; j < 4; j++) {
                asm volatile(
                    "mma.sync.aligned.m16n8k8.row.col.f32.tf32.tf32.f32 "
                    "{%0,%1,%2,%3}, {%4,%5,%6,%7}, {%8,%9}, {%0,%1,%2,%3};"
                    : "+f"(D[j][0]), "+f"(D[j][1]), "+f"(D[j][2]), "+f"(D[j][3])
                    : "r"(a0), "r"(a1), "r"(a2), "r"(a3),
                      "r"(B[j][s][0]), "r"(B[j][s][1]));
            }
        }

        // Epilogue: bfly-merge D halves into float4, coalesced vector atomics.
        float* orow = out + (size_t)y * C_OUT + colb;
#pragma unroll
        for (int j = 0; j < 4; j++) {
            float s0 = __shfl_xor_sync(0xffffffffu, odd ? D[j][0] : D[j][2], 1);
            float s1 = __shfl_xor_sync(0xffffffffu, odd ? D[j][1] : D[j][3], 1);
            float v0 = odd ? s0 : D[j][0];
            float v1 = odd ? s1 : D[j][1];
            float v2 = odd ? D[j][2] : s0;
            float v3 = odd ? D[j][3] : s1;
            asm volatile("red.global.add.v4.f32 [%0], {%1,%2,%3,%4};"
                         :: "l"(orow + 8 * j), "f"(v0), "f"(v1), "f"(v2), "f"(v3)
                         : "memory");
        }
    }
}

// ---------------------------------------------------------------------------
// Inputs (metadata order): in_feature f32[N_VOX,32], kernel f32[27,32,32],
// bias f32[32], nbmap i32[M,2], nbsizes i32[27]. Output f32[N_VOX,32].
// ---------------------------------------------------------------------------
extern "C" void kernel_launch(void* const* d_in, const int* in_sizes, int n_in,
                              void* d_out, int out_size) {
    const float*  in_feature = (const float*)d_in[0];
    const float*  kernel_w   = (const float*)d_in[1];
    const float4* bias4      = (const float4*)d_in[2];
    const int*    nbmap      = (const int*)d_in[3];
    float*        out        = (float*)d_out;

    init_bias_kernel<<<(N_VOX * 8 + 255) / 256, 256>>>((float4*)out, bias4);
    conv_mma_kernel<<<GRID, TPB>>>(in_feature, kernel_w, nbmap, out);
}

// round 5
// speedup vs baseline: 2.3913x; 1.1048x over previous
#include <cuda_runtime.h>
#include <cstdint>

#define K3          27
#define PAIRS_PER_K 131072
#define N_VOX       262144
#define C_IN        32
#define C_OUT       32
#define M_TOTAL     (K3 * PAIRS_PER_K)

#define TILE        128                     // pairs per MMA tile (8 warps x 16)
#define NT          8                       // tiles per block (same k)
#define TPB         256
#define TILES_PER_K (PAIRS_PER_K / TILE)    // 1024 (divisible by NT)
#define GRID        (M_TOTAL / TILE / NT)   // 3456
#define RS          36                      // A smem row stride in floats (144B)

// ---------------------------------------------------------------------------
// Kernel 1: initialize output with bias (d_out is poisoned by harness).
// ---------------------------------------------------------------------------
__global__ void init_bias_kernel(float4* __restrict__ out,
                                 const float4* __restrict__ bias4) {
    int t = blockIdx.x * blockDim.x + threadIdx.x;
    if (t < N_VOX * 8) out[t] = bias4[t & 7];
}

__device__ __forceinline__ uint32_t f2tf32(float x) {
    uint32_t r;
    asm("cvt.rna.tf32.f32 %0, %1;" : "=r"(r) : "f"(x));
    return r;
}

// ---------------------------------------------------------------------------
// Kernel 2: cp.async gather -> tf32 mma.sync (m16n8k8, B frags from a
// per-lane smem table) -> shfl-merged coalesced red.global.add.v4 scatter.
// j-outer loop keeps live regs low (A frags 16, D 4) -> 4 CTAs/SM.
// ---------------------------------------------------------------------------
__global__ void __launch_bounds__(TPB, 4)
conv_mma_kernel(const float* __restrict__ in_feature,   // [N_VOX][32]
                const float* __restrict__ kernel_w,     // [K3][32][32]
                const int*   __restrict__ nbmap,        // [M][2] (src,dst)
                float*       __restrict__ out)          // [N_VOX][32]
{
    __shared__ __align__(16) float As[2][TILE * RS];    // 2 x 18432B
    __shared__ __align__(16) uint2 Bsm[512];            // 4KB: [(j*4+s)*32+lane]

    const int tid  = threadIdx.x;
    const int wid  = tid >> 5;
    const int lane = tid & 31;

    const int tile0 = blockIdx.x * NT;
    const int k     = tile0 / TILES_PER_K;

    // ---- Build per-lane B fragment table (once per block) ----
    // Entry e = (j*4+s)*32 + lane:  b0=(k=8s+bk, n=8j+bn), b1=(k+4, n).
    {
        const float* wk = kernel_w + (size_t)k * (C_IN * C_OUT);
#pragma unroll
        for (int r = 0; r < 2; r++) {
            const int e  = tid + 256 * r;
            const int el = e & 31, s = (e >> 5) & 3, j = e >> 7;
            const int bk = el & 3, bn = el >> 2;
            uint2 b;
            b.x = f2tf32(wk[(8 * s + bk    ) * C_OUT + 8 * j + bn]);
            b.y = f2tf32(wk[(8 * s + bk + 4) * C_OUT + 8 * j + bn]);
            Bsm[e] = b;
        }
    }

    // ---- gather tile t into buffer buf: 1024 x cp.async.cg 16B ----
    auto gather = [&](int t, int buf) {
        const size_t pbase = (size_t)(tile0 + t) * TILE;
        const int ch = tid & 7;
#pragma unroll
        for (int jj = 0; jj < 4; jj++) {
            const int row = (tid >> 3) + 32 * jj;
            const int v   = nbmap[2 * (pbase + row)];         // src voxel
            const float* src = in_feature + (size_t)v * C_IN + ch * 4;
            const uint32_t dst =
                (uint32_t)__cvta_generic_to_shared(&As[buf][row * RS + ch * 4]);
            asm volatile("cp.async.cg.shared.global [%0], [%1], 16;"
                         :: "r"(dst), "l"(src));
        }
        asm volatile("cp.async.commit_group;" ::: "memory");
    };

    gather(0, 0);

    const int ar   = lane >> 2;                       // frag row-in-8
    const int ac   = lane & 3;                        // frag col-in-4
    const int rloc = 16 * wid + ar + 8 * (lane & 1);  // this lane's output row
    const int colb = (lane & 2) << 1;                 // 0 or 4
    const bool odd = lane & 1;

    for (int t = 0; t < NT; t++) {
        const int buf = t & 1;
        asm volatile("cp.async.wait_group 0;" ::: "memory");
        __syncthreads();                              // A(t) + Bsm ready

        if (t + 1 < NT) gather(t + 1, buf ^ 1);       // overlap with compute

        // destination voxel for this lane's merged row
        const int y = nbmap[2 * ((size_t)(tile0 + t) * TILE + rloc) + 1];
        float* orow = out + (size_t)y * C_OUT + colb;

        // A fragments: load + convert once, reuse across all 4 n8-tiles.
        const float* Ab = &As[buf][(16 * wid + ar) * RS];
        uint32_t A0[4], A1[4], A2[4], A3[4];
#pragma unroll
        for (int s = 0; s < 4; s++) {
            A0[s] = f2tf32(Ab[8 * s + ac]);
            A1[s] = f2tf32(Ab[8 * RS + 8 * s + ac]);
            A2[s] = f2tf32(Ab[8 * s + ac + 4]);
            A3[s] = f2tf32(Ab[8 * RS + 8 * s + ac + 4]);
        }

#pragma unroll
        for (int j = 0; j < 4; j++) {
            float D0 = 0.f, D1 = 0.f, D2 = 0.f, D3 = 0.f;
#pragma unroll
            for (int s = 0; s < 4; s++) {
                const uint2 b = Bsm[(j * 4 + s) * 32 + lane];
                asm volatile(
                    "mma.sync.aligned.m16n8k8.row.col.f32.tf32.tf32.f32 "
                    "{%0,%1,%2,%3}, {%4,%5,%6,%7}, {%8,%9}, {%0,%1,%2,%3};"
                    : "+f"(D0), "+f"(D1), "+f"(D2), "+f"(D3)
                    : "r"(A0[s]), "r"(A1[s]), "r"(A2[s]), "r"(A3[s]),
                      "r"(b.x), "r"(b.y));
            }
            // bfly-merge this j's D halves into one float4 per lane, then red.
            float s0 = __shfl_xor_sync(0xffffffffu, odd ? D0 : D2, 1);
            float s1 = __shfl_xor_sync(0xffffffffu, odd ? D1 : D3, 1);
            float v0 = odd ? s0 : D0;
            float v1 = odd ? s1 : D1;
            float v2 = odd ? D2 : s0;
            float v3 = odd ? D3 : s1;
            asm volatile("red.global.add.v4.f32 [%0], {%1,%2,%3,%4};"
                         :: "l"(orow + 8 * j), "f"(v0), "f"(v1), "f"(v2), "f"(v3)
                         : "memory");
        }
    }
}

// ---------------------------------------------------------------------------
// Inputs (metadata order): in_feature f32[N_VOX,32], kernel f32[27,32,32],
// bias f32[32], nbmap i32[M,2], nbsizes i32[27]. Output f32[N_VOX,32].
// ---------------------------------------------------------------------------
extern "C" void kernel_launch(void* const* d_in, const int* in_sizes, int n_in,
                              void* d_out, int out_size) {
    const float*  in_feature = (const float*)d_in[0];
    const float*  kernel_w   = (const float*)d_in[1];
    const float4* bias4      = (const float4*)d_in[2];
    const int*    nbmap      = (const int*)d_in[3];
    float*        out        = (float*)d_out;

    init_bias_kernel<<<(N_VOX * 8 + 255) / 256, 256>>>((float4*)out, bias4);
    conv_mma_kernel<<<GRID, TPB>>>(in_feature, kernel_w, nbmap, out);
}